// round 6
// baseline (speedup 1.0000x reference)
#include <cuda_runtime.h>

#define EPS 1e-7f

constexpr int T = 32;
constexpr int S = 2048;
constexpr int B = 512;
constexpr int SW = 8;                 // warps per block = s per block
constexpr int BTILE = 8;              // b per tile
constexpr int BGROUPS = 4;
constexpr int BPG = B / BGROUPS;      // 128
constexpr int NSB = S / SW;           // 256
constexpr int BT = B * T;             // 16384
constexpr int NTILES = BPG / BTILE;   // 16

constexpr int BST = 36;               // float stride per b in xs
constexpr int XROW = BTILE * BST + 4; // 292 floats per s-row
constexpr int XS = SW * XROW;         // 2336
constexpr int OPB = 296;              // per-b stride in op
constexpr int OPSZ = BTILE * OPB;     // 2368
// static smem: 2*(XS+OPSZ)*4 = 37632 B

__device__ float g_partial[(size_t)NSB * BT];   // 16.8 MB deterministic scratch
__device__ float g_partial2[16 * BT];

__device__ __forceinline__ float tanh_approx(float x) {
    float y; asm("tanh.approx.f32 %0, %1;" : "=f"(y) : "f"(x)); return y;
}
__device__ __forceinline__ unsigned long long pack2(float lo, float hi) {
    unsigned long long r;
    asm("mov.b64 %0, {%1, %2};" : "=l"(r) : "f"(lo), "f"(hi));
    return r;
}
__device__ __forceinline__ void fma2(unsigned long long& d, unsigned long long a,
                                     unsigned long long b, unsigned long long c) {
    asm("fma.rn.f32x2 %0, %1, %2, %3;" : "=l"(d) : "l"(a), "l"(b), "l"(c));
}
__device__ __forceinline__ float hsum2(unsigned long long a) {
    float lo, hi;
    asm("mov.b64 {%0, %1}, %2;" : "=f"(lo), "=f"(hi) : "l"(a));
    return lo + hi;
}

__global__ __launch_bounds__(256, 1) void attn_main(
    const float* __restrict__ inp, const float* __restrict__ msk,
    const float* __restrict__ W,   const float* __restrict__ bias)
{
    __shared__ float sm[2 * XS + 2 * OPSZ];
    float* xsb[2] = { sm, sm + XS };
    float* opb[2] = { sm + 2 * XS, sm + 2 * XS + OPSZ };

    const int tid  = threadIdx.x;
    const int w    = tid >> 5;          // warp id = local s
    const int lane = tid & 31;
    const int ug   = lane & 7;          // lane owns u = ug + 8j, j=0..3
    const int bq   = lane >> 3;         // b slot within pass
    const int s0   = blockIdx.x * SW;
    const int bb   = blockIdx.y * BPG;
    const int s    = s0 + w;

    // W register-resident: 64 packed f32x2 = 128 regs (256 thr -> 255-reg budget)
    unsigned long long w2[64];
    {
        const float* Wp = W + s * (T * T) + ug;
        #pragma unroll
        for (int j = 0; j < 4; j++)
            #pragma unroll
            for (int k = 0; k < 16; k++)
                w2[j * 16 + k] = pack2(Wp[(2 * k) * 32 + 8 * j],
                                       Wp[(2 * k + 1) * 32 + 8 * j]);
    }
    float brg[4];
    #pragma unroll
    for (int j = 0; j < 4; j++) brg[j] = bias[s * 32 + ug + 8 * j];

    // staging mapping (vectorized): warp covers 16 t-rows x 32B = 512B / LDG.128
    const int q  = tid >> 6;            // 0..3 -> handles b = q and q+4
    const int tt = (tid >> 1) & 31;     // t
    const int sh = tid & 1;             // s-half (float4)
    const float* ipb = inp + (size_t)bb * (T * S) + (size_t)tt * S + s0 + 4 * sh;
    const float* mpb = msk + (size_t)bb * (T * S) + (size_t)tt * S + s0 + 4 * sh;

    float4 px[2];
    #pragma unroll
    for (int j = 0; j < 2; j++) {
        size_t off = (size_t)(q + 4 * j) * (T * S);
        float4 iv = *(const float4*)(ipb + off);
        float4 mv = *(const float4*)(mpb + off);
        px[j] = make_float4(iv.x * mv.x, iv.y * mv.y, iv.z * mv.z, iv.w * mv.w);
    }

    const int rbl = tid >> 5;           // reduce role: b
    const int ru  = lane;               // reduce role: u

    for (int bt = 0; bt < BPG; bt += BTILE) {
        const int ti  = bt / BTILE;
        const int cur = ti & 1;

        // ---- stage x -> xs[cur][4sh+i][bl][tt]  (conflict-free STS) ----
        {
            float* xr = xsb[cur] + (4 * sh) * XROW + tt;
            #pragma unroll
            for (int j = 0; j < 2; j++) {
                float* p = xr + (q + 4 * j) * BST;
                p[0]        = px[j].x;
                p[XROW]     = px[j].y;
                p[2 * XROW] = px[j].z;
                p[3 * XROW] = px[j].w;
            }
        }

        // ---- prefetch next tile BEFORE the barrier (loads fly during wait) ----
        if (bt + BTILE < BPG) {
            #pragma unroll
            for (int j = 0; j < 2; j++) {
                size_t off = (size_t)(bt + BTILE + q + 4 * j) * (T * S);
                float4 iv = *(const float4*)(ipb + off);
                float4 mv = *(const float4*)(mpb + off);
                px[j] = make_float4(iv.x * mv.x, iv.y * mv.y, iv.z * mv.z, iv.w * mv.w);
            }
        }
        __syncthreads();

        // ---- overlapped: reduce previous tile's op -> g_partial ----
        if (ti > 0) {
            const float* r = opb[cur ^ 1] + rbl * OPB + ru * 9;
            float sum = 0.f;
            #pragma unroll
            for (int k = 0; k < SW; k++) sum += r[k];
            g_partial[(size_t)blockIdx.x * BT +
                      (size_t)(bb + bt - BTILE + rbl) * T + ru] = sum;
        }

        // ---- both passes' matvecs together: 8 independent FMA chains ----
        const float* xb0 = xsb[cur] + w * XROW + bq * BST;        // b = bq
        const float* xb1 = xb0 + 4 * BST;                          // b = bq+4
        const ulonglong2* xq0 = (const ulonglong2*)xb0;
        const ulonglong2* xq1 = (const ulonglong2*)xb1;

        unsigned long long a0 = 0, a1 = 0, a2 = 0, a3 = 0;
        unsigned long long c0 = 0, c1 = 0, c2 = 0, c3 = 0;
        #pragma unroll
        for (int h = 0; h < 8; h++) {
            ulonglong2 v0 = xq0[h];
            ulonglong2 v1 = xq1[h];
            fma2(a0, v0.x, w2[0 * 16 + 2 * h], a0);
            fma2(a1, v0.x, w2[1 * 16 + 2 * h], a1);
            fma2(a2, v0.x, w2[2 * 16 + 2 * h], a2);
            fma2(a3, v0.x, w2[3 * 16 + 2 * h], a3);
            fma2(c0, v1.x, w2[0 * 16 + 2 * h], c0);
            fma2(c1, v1.x, w2[1 * 16 + 2 * h], c1);
            fma2(c2, v1.x, w2[2 * 16 + 2 * h], c2);
            fma2(c3, v1.x, w2[3 * 16 + 2 * h], c3);
            fma2(a0, v0.y, w2[0 * 16 + 2 * h + 1], a0);
            fma2(a1, v0.y, w2[1 * 16 + 2 * h + 1], a1);
            fma2(a2, v0.y, w2[2 * 16 + 2 * h + 1], a2);
            fma2(a3, v0.y, w2[3 * 16 + 2 * h + 1], a3);
            fma2(c0, v1.y, w2[0 * 16 + 2 * h + 1], c0);
            fma2(c1, v1.y, w2[1 * 16 + 2 * h + 1], c1);
            fma2(c2, v1.y, w2[2 * 16 + 2 * h + 1], c2);
            fma2(c3, v1.y, w2[3 * 16 + 2 * h + 1], c3);
        }

        // ---- both epilogues interleaved (2 independent chains) ----
        float e0 = __expf(tanh_approx(hsum2(a0) + brg[0]));
        float f0 = __expf(tanh_approx(hsum2(c0) + brg[0]));
        float e1 = __expf(tanh_approx(hsum2(a1) + brg[1]));
        float f1 = __expf(tanh_approx(hsum2(c1) + brg[1]));
        float e2 = __expf(tanh_approx(hsum2(a2) + brg[2]));
        float f2 = __expf(tanh_approx(hsum2(c2) + brg[2]));
        float e3 = __expf(tanh_approx(hsum2(a3) + brg[3]));
        float f3 = __expf(tanh_approx(hsum2(c3) + brg[3]));

        float r0 = (e0 + e1) + (e2 + e3);
        float r1 = (f0 + f1) + (f2 + f3);
        r0 += __shfl_xor_sync(~0u, r0, 1);
        r1 += __shfl_xor_sync(~0u, r1, 1);
        r0 += __shfl_xor_sync(~0u, r0, 2);
        r1 += __shfl_xor_sync(~0u, r1, 2);
        r0 += __shfl_xor_sync(~0u, r0, 4);
        r1 += __shfl_xor_sync(~0u, r1, 4);

        float inv0 = __fdividef(1.f, r0 + EPS);
        float inv1 = __fdividef(1.f, r1 + EPS);

        float* od0 = opb[cur] + bq * OPB + ug * 9 + w;
        float* od1 = od0 + 4 * OPB;
        od0[0]      = e0 * inv0 * xb0[ug];
        od0[8 * 9]  = e1 * inv0 * xb0[ug + 8];
        od0[16 * 9] = e2 * inv0 * xb0[ug + 16];
        od0[24 * 9] = e3 * inv0 * xb0[ug + 24];
        od1[0]      = f0 * inv1 * xb1[ug];
        od1[8 * 9]  = f1 * inv1 * xb1[ug + 8];
        od1[16 * 9] = f2 * inv1 * xb1[ug + 16];
        od1[24 * 9] = f3 * inv1 * xb1[ug + 24];
    }

    // ---- final tile's reduction ----
    __syncthreads();
    {
        const int lastcur = (NTILES - 1) & 1;
        const float* r = opb[lastcur] + rbl * OPB + ru * 9;
        float sum = 0.f;
        #pragma unroll
        for (int k = 0; k < SW; k++) sum += r[k];
        g_partial[(size_t)blockIdx.x * BT +
                  (size_t)(bb + BPG - BTILE + rbl) * T + ru] = sum;
    }
}

__global__ void attn_reduceA()
{
    const int i = blockIdx.x * 256 + threadIdx.x;
    const int j = blockIdx.y;                      // 0..15
    const float* p = g_partial + (size_t)j * 16 * BT + i;
    float s = 0.f;
    #pragma unroll
    for (int k = 0; k < 16; k++) s += p[(size_t)k * BT];
    g_partial2[j * BT + i] = s;
}

__global__ void attn_reduceB(float* __restrict__ out)
{
    const int i = blockIdx.x * 256 + threadIdx.x;
    float s = 0.f;
    #pragma unroll
    for (int j = 0; j < 16; j++) s += g_partial2[j * BT + i];
    out[i] = s;
}

extern "C" void kernel_launch(void* const* d_in, const int* in_sizes, int n_in,
                              void* d_out, int out_size)
{
    const float* inp  = (const float*)d_in[0];
    const float* msk  = (const float*)d_in[1];
    const float* W    = (const float*)d_in[2];
    const float* bias = (const float*)d_in[3];
    float* out = (float*)d_out;

    dim3 grid(NSB, BGROUPS);
    attn_main<<<grid, 256>>>(inp, msk, W, bias);
    attn_reduceA<<<dim3(BT / 256, 16), 256>>>();
    attn_reduceB<<<BT / 256, 256>>>(out);
}

// round 8
// speedup vs baseline: 1.4455x; 1.4455x over previous
#include <cuda_runtime.h>

#define EPS 1e-7f

constexpr int T  = 32;
constexpr int S  = 2048;
constexpr int NB = 512;               // batch
constexpr int SW = 16;                // warps per block = s per block
constexpr int BTILE = 8;              // b per tile
constexpr int BGROUPS = 2;
constexpr int BPG = NB / BGROUPS;     // 256
constexpr int NSB = S / SW;           // 128
constexpr int BT  = NB * T;           // 16384
constexpr int NTILES = BPG / BTILE;   // 32

constexpr int BST  = 36;              // per-b float stride in xs
constexpr int XROW = BTILE * BST + 4; // 292 floats per s-row
constexpr int XS   = SW * XROW;       // 4672
constexpr int WST  = 36;              // per-warp(s) stride in op (4-float aligned, 4 mod 32)
constexpr int OPB  = SW * WST + 8;    // 584 per-b stride
constexpr int OPSZ = BTILE * OPB;     // 4672
constexpr int SMEM_BYTES = 2 * (XS + OPSZ) * 4;   // 74752 B (dynamic)

__device__ float g_partial[(size_t)NSB * BT];     // 8.4 MB deterministic scratch
__device__ float g_partial2[16 * BT];

__device__ __forceinline__ float tanh_approx(float x) {
    float y; asm("tanh.approx.f32 %0, %1;" : "=f"(y) : "f"(x)); return y;
}
__device__ __forceinline__ unsigned long long pack2(float lo, float hi) {
    unsigned long long r;
    asm("mov.b64 %0, {%1, %2};" : "=l"(r) : "f"(lo), "f"(hi));
    return r;
}
__device__ __forceinline__ void fma2(unsigned long long& d, unsigned long long a,
                                     unsigned long long b, unsigned long long c) {
    asm("fma.rn.f32x2 %0, %1, %2, %3;" : "=l"(d) : "l"(a), "l"(b), "l"(c));
}
__device__ __forceinline__ float hsum2(unsigned long long a) {
    float lo, hi;
    asm("mov.b64 {%0, %1}, %2;" : "=f"(lo), "=f"(hi) : "l"(a));
    return lo + hi;
}

__global__ __launch_bounds__(512, 1) void attn_main(
    const float* __restrict__ inp, const float* __restrict__ msk,
    const float* __restrict__ W,   const float* __restrict__ bias)
{
    extern __shared__ float sm[];
    float* xsb[2] = { sm, sm + XS };
    float* opb[2] = { sm + 2 * XS, sm + 2 * XS + OPSZ };

    const int tid  = threadIdx.x;
    const int w    = tid >> 5;          // warp = local s
    const int lane = tid & 31;
    const int ug   = lane & 7;          // u-group: u = 4ug..4ug+3
    const int th   = lane >> 3;         // t-quarter: t = 8th..8th+7
    const int s0   = blockIdx.x * SW;
    const int bb   = blockIdx.y * BPG;
    const int s    = s0 + w;

    // W: lane holds W[t in its quarter][4 u] = 16 f32x2 = 32 regs. No duplication.
    unsigned long long w2[16];          // [j*4 + k], k = local t-pair
    float brg[4];
    {
        const float* Wp = W + s * (T * T) + (8 * th) * 32 + 4 * ug;
        float4 wa[8];
        #pragma unroll
        for (int r = 0; r < 8; r++) wa[r] = *(const float4*)(Wp + r * 32);
        #pragma unroll
        for (int k = 0; k < 4; k++) {
            w2[0 * 4 + k] = pack2(wa[2 * k].x, wa[2 * k + 1].x);
            w2[1 * 4 + k] = pack2(wa[2 * k].y, wa[2 * k + 1].y);
            w2[2 * 4 + k] = pack2(wa[2 * k].z, wa[2 * k + 1].z);
            w2[3 * 4 + k] = pack2(wa[2 * k].w, wa[2 * k + 1].w);
        }
        float4 bv = *(const float4*)(bias + s * 32 + 4 * ug);
        brg[0] = bv.x; brg[1] = bv.y; brg[2] = bv.z; brg[3] = bv.w;
    }

    // staging: sh = s-quad, tt = t, q -> b = q, q+4.  512B/LDG.128 per warp.
    const int sh = tid & 3;
    const int tt = (tid >> 2) & 31;
    const int q  = tid >> 7;            // 0..3
    const float* ipb = inp + (size_t)bb * (T * S) + (size_t)tt * S + s0 + 4 * sh;
    const float* mpb = msk + (size_t)bb * (T * S) + (size_t)tt * S + s0 + 4 * sh;

    float4 px[2];
    #pragma unroll
    for (int j = 0; j < 2; j++) {
        size_t off = (size_t)(q + 4 * j) * (T * S);
        float4 iv = *(const float4*)(ipb + off);
        float4 mv = *(const float4*)(mpb + off);
        px[j] = make_float4(iv.x * mv.x, iv.y * mv.y, iv.z * mv.z, iv.w * mv.w);
    }

    const bool keep1 = th & 1;          // reduce-scatter selectors
    const bool keep2 = th & 2;

    for (int bt = 0; bt < BPG; bt += BTILE) {
        const int ti  = bt / BTILE;
        const int cur = ti & 1;

        // ---- stage x -> xs[cur][4sh+i][b][tt] ----
        {
            float* xr = xsb[cur] + (4 * sh) * XROW + tt;
            #pragma unroll
            for (int j = 0; j < 2; j++) {
                float* p = xr + (q + 4 * j) * BST;
                p[0]        = px[j].x;
                p[XROW]     = px[j].y;
                p[2 * XROW] = px[j].z;
                p[3 * XROW] = px[j].w;
            }
        }

        // ---- prefetch next tile before the barrier ----
        if (bt + BTILE < BPG) {
            #pragma unroll
            for (int j = 0; j < 2; j++) {
                size_t off = (size_t)(bt + BTILE + q + 4 * j) * (T * S);
                float4 iv = *(const float4*)(ipb + off);
                float4 mv = *(const float4*)(mpb + off);
                px[j] = make_float4(iv.x * mv.x, iv.y * mv.y, iv.z * mv.z, iv.w * mv.w);
            }
        }
        __syncthreads();

        // ---- overlapped: reduce previous tile's op -> g_partial ----
        if (ti > 0 && tid < BTILE * 32) {
            const int rb = tid >> 5, ru = tid & 31;
            const float* r = opb[cur ^ 1] + rb * OPB + ru;
            float sum = 0.f;
            #pragma unroll
            for (int k = 0; k < SW; k++) sum += r[k * WST];
            g_partial[(size_t)blockIdx.x * BT +
                      (size_t)(bb + bt - BTILE + rb) * T + ru] = sum;
        }

        // ---- compute: 2 groups of 4 b; lane accumulates its t-quarter for all 4 ----
        #pragma unroll
        for (int g = 0; g < 2; g++) {
            unsigned long long acc[4][4];
            #pragma unroll
            for (int bp = 0; bp < 4; bp++)
                #pragma unroll
                for (int j = 0; j < 4; j++) acc[bp][j] = 0;

            #pragma unroll
            for (int bp = 0; bp < 4; bp++) {
                const float* xb = xsb[cur] + w * XROW + (4 * g + bp) * BST + 8 * th;
                ulonglong2 v0 = *(const ulonglong2*)(xb);
                ulonglong2 v1 = *(const ulonglong2*)(xb + 4);
                #pragma unroll
                for (int j = 0; j < 4; j++) {
                    fma2(acc[bp][j], v0.x, w2[j * 4 + 0], acc[bp][j]);
                    fma2(acc[bp][j], v0.y, w2[j * 4 + 1], acc[bp][j]);
                    fma2(acc[bp][j], v1.x, w2[j * 4 + 2], acc[bp][j]);
                    fma2(acc[bp][j], v1.y, w2[j * 4 + 3], acc[bp][j]);
                }
            }

            // partial z per (b', j), then reduce-scatter over th:
            // lane th ends with full z for b = 4g + th (4 u values).
            float z[4];
            #pragma unroll
            for (int j = 0; j < 4; j++) {
                float zp0 = hsum2(acc[0][j]);
                float zp1 = hsum2(acc[1][j]);
                float zp2 = hsum2(acc[2][j]);
                float zp3 = hsum2(acc[3][j]);
                // stage 1: xor 8 (th bit0)
                float give0 = keep1 ? zp0 : zp1;
                float give1 = keep1 ? zp2 : zp3;
                float r0 = __shfl_xor_sync(~0u, give0, 8);
                float r1 = __shfl_xor_sync(~0u, give1, 8);
                float a  = (keep1 ? zp1 : zp0) + r0;   // bl = th&1
                float b_ = (keep1 ? zp3 : zp2) + r1;   // bl = (th&1)+2
                // stage 2: xor 16 (th bit1)
                float give = keep2 ? a : b_;
                float r2 = __shfl_xor_sync(~0u, give, 16);
                z[j] = (keep2 ? b_ : a) + r2;           // bl = th
            }

            float e0 = __expf(tanh_approx(z[0] + brg[0]));
            float e1 = __expf(tanh_approx(z[1] + brg[1]));
            float e2 = __expf(tanh_approx(z[2] + brg[2]));
            float e3 = __expf(tanh_approx(z[3] + brg[3]));

            float r = (e0 + e1) + (e2 + e3);
            r += __shfl_xor_sync(~0u, r, 1);
            r += __shfl_xor_sync(~0u, r, 2);
            r += __shfl_xor_sync(~0u, r, 4);   // sum over 32 u (ug lanes, same th/b)

            float inv = __fdividef(1.f, r + EPS);

            const float* xwb = xsb[cur] + w * XROW + (4 * g + th) * BST;
            float4 xu = *(const float4*)(xwb + 4 * ug);   // x at t = u, this lane's b

            float* od = opb[cur] + (4 * g + th) * OPB + w * WST + 4 * ug;
            *(float4*)od = make_float4(e0 * inv * xu.x, e1 * inv * xu.y,
                                       e2 * inv * xu.z, e3 * inv * xu.w);
        }
    }

    // ---- final tile's reduction ----
    __syncthreads();
    if (tid < BTILE * 32) {
        const int rb = tid >> 5, ru = tid & 31;
        const int lastcur = (NTILES - 1) & 1;
        const float* r = opb[lastcur] + rb * OPB + ru;
        float sum = 0.f;
        #pragma unroll
        for (int k = 0; k < SW; k++) sum += r[k * WST];
        g_partial[(size_t)blockIdx.x * BT +
                  (size_t)(bb + BPG - BTILE + rb) * T + ru] = sum;
    }
}

// stage A: 16 groups x 8 slices
__global__ void attn_reduceA()
{
    const int i = blockIdx.x * 256 + threadIdx.x;
    const int j = blockIdx.y;                    // 0..15
    const float* p = g_partial + (size_t)j * 8 * BT + i;
    float s = 0.f;
    #pragma unroll
    for (int k = 0; k < 8; k++) s += p[(size_t)k * BT];
    g_partial2[j * BT + i] = s;
}

__global__ void attn_reduceB(float* __restrict__ out)
{
    const int i = blockIdx.x * 256 + threadIdx.x;
    float s = 0.f;
    #pragma unroll
    for (int j = 0; j < 16; j++) s += g_partial2[j * BT + i];
    out[i] = s;
}

extern "C" void kernel_launch(void* const* d_in, const int* in_sizes, int n_in,
                              void* d_out, int out_size)
{
    const float* inp  = (const float*)d_in[0];
    const float* msk  = (const float*)d_in[1];
    const float* W    = (const float*)d_in[2];
    const float* bias = (const float*)d_in[3];
    float* out = (float*)d_out;

    cudaFuncSetAttribute(attn_main, cudaFuncAttributeMaxDynamicSharedMemorySize, SMEM_BYTES);

    dim3 grid(NSB, BGROUPS);
    attn_main<<<grid, 512, SMEM_BYTES>>>(inp, msk, W, bias);
    attn_reduceA<<<dim3(BT / 256, 16), 256>>>();
    attn_reduceB<<<BT / 256, 256>>>(out);
}

// round 10
// speedup vs baseline: 1.5712x; 1.0870x over previous
#include <cuda_runtime.h>

#define EPS 1e-7f

constexpr int T  = 32;
constexpr int S  = 2048;
constexpr int NB = 512;               // batch
constexpr int SW = 8;                 // warps per block = s per block
constexpr int BTILE = 8;              // b per tile
constexpr int BGROUPS = 8;
constexpr int BPG = NB / BGROUPS;     // 64
constexpr int NSB = S / SW;           // 256
constexpr int BT  = NB * T;           // 16384
constexpr int NTILES = BPG / BTILE;   // 8

constexpr int BST  = 36;              // per-b float stride in xs
constexpr int XROW = BTILE * BST + 4; // 292 floats per s-row
constexpr int XS   = SW * XROW;       // 2336
constexpr int WST  = 36;              // per-warp(s) stride in op
constexpr int OPB  = SW * WST + 8;    // 296 per-b stride
constexpr int OPSZ = BTILE * OPB;     // 2368
// static smem: 2*(XS+OPSZ)*4 = 37632 B -> 2 blocks/SM fit easily

__device__ float g_partial[(size_t)NSB * BT];     // 16.8 MB deterministic scratch
__device__ float g_partial2[16 * BT];

__device__ __forceinline__ float tanh_approx(float x) {
    float y; asm("tanh.approx.f32 %0, %1;" : "=f"(y) : "f"(x)); return y;
}
__device__ __forceinline__ unsigned long long pack2(float lo, float hi) {
    unsigned long long r;
    asm("mov.b64 %0, {%1, %2};" : "=l"(r) : "f"(lo), "f"(hi));
    return r;
}
__device__ __forceinline__ void fma2(unsigned long long& d, unsigned long long a,
                                     unsigned long long b, unsigned long long c) {
    asm("fma.rn.f32x2 %0, %1, %2, %3;" : "=l"(d) : "l"(a), "l"(b), "l"(c));
}
__device__ __forceinline__ float hsum2(unsigned long long a) {
    float lo, hi;
    asm("mov.b64 {%0, %1}, %2;" : "=f"(lo), "=f"(hi) : "l"(a));
    return lo + hi;
}

__global__ __launch_bounds__(256, 2) void attn_main(
    const float* __restrict__ inp, const float* __restrict__ msk,
    const float* __restrict__ W,   const float* __restrict__ bias)
{
    __shared__ float sm[2 * (XS + OPSZ)];
    float* xsb[2] = { sm, sm + XS };
    float* opb[2] = { sm + 2 * XS, sm + 2 * XS + OPSZ };

    const int tid  = threadIdx.x;
    const int w    = tid >> 5;          // warp = local s
    const int lane = tid & 31;
    const int ug   = lane & 7;          // u-group: u = 4ug..4ug+3
    const int th   = lane >> 3;         // t-quarter: t = 8th..8th+7
    const int s0   = blockIdx.x * SW;
    const int bb   = blockIdx.y * BPG;
    const int s    = s0 + w;

    // W: lane holds W[8 t of its quarter][4 u] = 16 f32x2 = 32 regs, no duplication
    unsigned long long w2[16];
    float brg[4];
    {
        const float* Wp = W + s * (T * T) + (8 * th) * 32 + 4 * ug;
        float4 wa[8];
        #pragma unroll
        for (int r = 0; r < 8; r++) wa[r] = *(const float4*)(Wp + r * 32);
        #pragma unroll
        for (int k = 0; k < 4; k++) {
            w2[0 * 4 + k] = pack2(wa[2 * k].x, wa[2 * k + 1].x);
            w2[1 * 4 + k] = pack2(wa[2 * k].y, wa[2 * k + 1].y);
            w2[2 * 4 + k] = pack2(wa[2 * k].z, wa[2 * k + 1].z);
            w2[3 * 4 + k] = pack2(wa[2 * k].w, wa[2 * k + 1].w);
        }
        float4 bv = *(const float4*)(bias + s * 32 + 4 * ug);
        brg[0] = bv.x; brg[1] = bv.y; brg[2] = bv.z; brg[3] = bv.w;
    }

    // staging: warp covers 16 t-rows x 32B = 512B per LDG.128
    const int sh = tid & 1;             // s-half (float4 of the 8 s)
    const int tt = (tid >> 1) & 31;     // t
    const int q  = tid >> 6;            // 0..3 -> b = q, q+4
    const float* ipb = inp + (size_t)bb * (T * S) + (size_t)tt * S + s0 + 4 * sh;
    const float* mpb = msk + (size_t)bb * (T * S) + (size_t)tt * S + s0 + 4 * sh;

    float4 px[2];
    #pragma unroll
    for (int j = 0; j < 2; j++) {
        size_t off = (size_t)(q + 4 * j) * (T * S);
        float4 iv = *(const float4*)(ipb + off);
        float4 mv = *(const float4*)(mpb + off);
        px[j] = make_float4(iv.x * mv.x, iv.y * mv.y, iv.z * mv.z, iv.w * mv.w);
    }

    const bool keep1 = th & 1;
    const bool keep2 = th & 2;
    const int rb = tid >> 5, ru = tid & 31;   // reduce roles (all 256 threads)

    for (int bt = 0; bt < BPG; bt += BTILE) {
        const int ti  = bt / BTILE;
        const int cur = ti & 1;

        // ---- stage x -> xs[cur][4sh+i][b][tt]  (conflict-free STS) ----
        {
            float* xr = xsb[cur] + (4 * sh) * XROW + tt;
            #pragma unroll
            for (int j = 0; j < 2; j++) {
                float* p = xr + (q + 4 * j) * BST;
                p[0]        = px[j].x;
                p[XROW]     = px[j].y;
                p[2 * XROW] = px[j].z;
                p[3 * XROW] = px[j].w;
            }
        }

        // ---- prefetch next tile before the barrier ----
        if (bt + BTILE < BPG) {
            #pragma unroll
            for (int j = 0; j < 2; j++) {
                size_t off = (size_t)(bt + BTILE + q + 4 * j) * (T * S);
                float4 iv = *(const float4*)(ipb + off);
                float4 mv = *(const float4*)(mpb + off);
                px[j] = make_float4(iv.x * mv.x, iv.y * mv.y, iv.z * mv.z, iv.w * mv.w);
            }
        }
        __syncthreads();

        // ---- overlapped: reduce previous tile's op -> g_partial ----
        if (ti > 0) {
            const float* r = opb[cur ^ 1] + rb * OPB + ru;
            float sum = 0.f;
            #pragma unroll
            for (int k = 0; k < SW; k++) sum += r[k * WST];
            g_partial[(size_t)blockIdx.x * BT +
                      (size_t)(bb + bt - BTILE + rb) * T + ru] = sum;
        }

        // ---- compute: 2 groups of 4 b; lane accumulates its t-quarter ----
        #pragma unroll
        for (int g = 0; g < 2; g++) {
            unsigned long long acc[4][4];
            #pragma unroll
            for (int bp = 0; bp < 4; bp++)
                #pragma unroll
                for (int j = 0; j < 4; j++) acc[bp][j] = 0;

            #pragma unroll
            for (int bp = 0; bp < 4; bp++) {
                const float* xb = xsb[cur] + w * XROW + (4 * g + bp) * BST + 8 * th;
                ulonglong2 v0 = *(const ulonglong2*)(xb);
                ulonglong2 v1 = *(const ulonglong2*)(xb + 4);
                #pragma unroll
                for (int j = 0; j < 4; j++) {
                    fma2(acc[bp][j], v0.x, w2[j * 4 + 0], acc[bp][j]);
                    fma2(acc[bp][j], v0.y, w2[j * 4 + 1], acc[bp][j]);
                    fma2(acc[bp][j], v1.x, w2[j * 4 + 2], acc[bp][j]);
                    fma2(acc[bp][j], v1.y, w2[j * 4 + 3], acc[bp][j]);
                }
            }

            // reduce-scatter over th: lane ends with full z for b = 4g + th
            float z[4];
            #pragma unroll
            for (int j = 0; j < 4; j++) {
                float zp0 = hsum2(acc[0][j]);
                float zp1 = hsum2(acc[1][j]);
                float zp2 = hsum2(acc[2][j]);
                float zp3 = hsum2(acc[3][j]);
                float give0 = keep1 ? zp0 : zp1;
                float give1 = keep1 ? zp2 : zp3;
                float r0 = __shfl_xor_sync(~0u, give0, 8);
                float r1 = __shfl_xor_sync(~0u, give1, 8);
                float a  = (keep1 ? zp1 : zp0) + r0;
                float b_ = (keep1 ? zp3 : zp2) + r1;
                float give = keep2 ? a : b_;
                float r2 = __shfl_xor_sync(~0u, give, 16);
                z[j] = (keep2 ? b_ : a) + r2;
            }

            float e0 = __expf(tanh_approx(z[0] + brg[0]));
            float e1 = __expf(tanh_approx(z[1] + brg[1]));
            float e2 = __expf(tanh_approx(z[2] + brg[2]));
            float e3 = __expf(tanh_approx(z[3] + brg[3]));

            float r = (e0 + e1) + (e2 + e3);
            r += __shfl_xor_sync(~0u, r, 1);
            r += __shfl_xor_sync(~0u, r, 2);
            r += __shfl_xor_sync(~0u, r, 4);

            float inv = __fdividef(1.f, r + EPS);

            const float* xwb = xsb[cur] + w * XROW + (4 * g + th) * BST;
            float4 xu = *(const float4*)(xwb + 4 * ug);

            float* od = opb[cur] + (4 * g + th) * OPB + w * WST + 4 * ug;
            *(float4*)od = make_float4(e0 * inv * xu.x, e1 * inv * xu.y,
                                       e2 * inv * xu.z, e3 * inv * xu.w);
        }
    }

    // ---- final tile's reduction ----
    __syncthreads();
    {
        const int lastcur = (NTILES - 1) & 1;
        const float* r = opb[lastcur] + rb * OPB + ru;
        float sum = 0.f;
        #pragma unroll
        for (int k = 0; k < SW; k++) sum += r[k * WST];
        g_partial[(size_t)blockIdx.x * BT +
                  (size_t)(bb + BPG - BTILE + rb) * T + ru] = sum;
    }
}

// stage A: 16 groups x 16 slices
__global__ void attn_reduceA()
{
    const int i = blockIdx.x * 256 + threadIdx.x;
    const int j = blockIdx.y;                    // 0..15
    const float* p = g_partial + (size_t)j * 16 * BT + i;
    float s = 0.f;
    #pragma unroll
    for (int k = 0; k < 16; k++) s += p[(size_t)k * BT];
    g_partial2[j * BT + i] = s;
}

__global__ void attn_reduceB(float* __restrict__ out)
{
    const int i = blockIdx.x * 256 + threadIdx.x;
    float s = 0.f;
    #pragma unroll
    for (int j = 0; j < 16; j++) s += g_partial2[j * BT + i];
    out[i] = s;
}

extern "C" void kernel_launch(void* const* d_in, const int* in_sizes, int n_in,
                              void* d_out, int out_size)
{
    const float* inp  = (const float*)d_in[0];
    const float* msk  = (const float*)d_in[1];
    const float* W    = (const float*)d_in[2];
    const float* bias = (const float*)d_in[3];
    float* out = (float*)d_out;

    dim3 grid(NSB, BGROUPS);
    attn_main<<<grid, 256>>>(inp, msk, W, bias);
    attn_reduceA<<<dim3(BT / 256, 16), 256>>>();
    attn_reduceB<<<BT / 256, 256>>>(out);
}